// round 9
// baseline (speedup 1.0000x reference)
#include <cuda_runtime.h>
#include <cstdint>

#define BSZ 2
#define NN  4096
#define JJ  3
#define CC  32
#define KO  32
#define MJ  (NN*JJ)               // 12288
#define BM  512
#define BKT 32
#define NTILES (NN/BM)            // 8
#define CHUNKS (MJ/BKT)           // 384
#define TOTAL_STEPS (BSZ*NTILES*CHUNKS)   // 6144
#define NBLK 148                  // one persistent block per SM
#define WS  36                    // padded stride: frag banks = 4*lg+lt, conflict-free
#define W_WORDS (BM*WS)           // 18432
#define T_WORDS (KO*WS)           // 1152
#define STAGE_WORDS (W_WORDS + T_WORDS)       // 19584
#define GEMM_SMEM (2 * STAGE_WORDS * 4)       // 156672 B

__device__ float g_t[BSZ * MJ * KO];          // t[b][mj][k] (tf32 bits)

__device__ __forceinline__ uint32_t f2tf32(float f) {
    uint32_t o;
    asm("cvt.rna.tf32.f32 %0, %1;" : "=r"(o) : "f"(f));
    return o;
}

// ---------------------------------------------------------------------------
// Fused: out[b][k][n] = bias[k]  AND  t[bm][j*32+k] = (1+2^-11)*sum_c cw*x
// ---------------------------------------------------------------------------
__global__ __launch_bounds__(256) void precompute_t_kernel(const float* __restrict__ x,
                                                           const float* __restrict__ cw,
                                                           float* __restrict__ out,
                                                           const float* __restrict__ cb) {
    __shared__ float cws[KO * 100];
    __shared__ float xs[16 * WS];

    const int tid = threadIdx.x;
    const int bm0 = blockIdx.x * 16;

    // out init: 512 elements per block, 2 per thread (same k, float2)
    {
        int idx = blockIdx.x * 512 + tid * 2;
        float bk = cb[(idx >> 12) & 31];
        *(float2*)(out + idx) = make_float2(bk, bk);
    }

#pragma unroll
    for (int p = 0; p < 3; ++p) {
        int idx = p * 256 + tid;               // 768 float4 of conv_w
        int r = idx / 24, cv = idx % 24;
        float4 v = ((const float4*)cw)[idx];
        *(float4*)(cws + r * 100 + cv * 4) = v;
    }
    if (tid < 128) {
        int r = tid >> 3, cv = tid & 7;
        float4 v = ((const float4*)(x + (size_t)bm0 * CC))[tid];
        *(float4*)(xs + r * WS + cv * 4) = v;
    }
    __syncthreads();

#pragma unroll
    for (int p = 0; p < 6; ++p) {
        int o = p * 256 + tid;                 // 0..1535
        int bm = o / 96, jk = o % 96;
        int j = jk >> 5, k = jk & 31;
        const float* xr = xs + bm * WS;
        const float* wr = cws + k * 100 + j * 32;
        float s = 0.f;
#pragma unroll
        for (int cv = 0; cv < 8; ++cv) {
            float4 xv = *(const float4*)(xr + cv * 4);
            float4 wv = *(const float4*)(wr + cv * 4);
            s = fmaf(xv.x, wv.x, s);
            s = fmaf(xv.y, wv.y, s);
            s = fmaf(xv.z, wv.z, s);
            s = fmaf(xv.w, wv.w, s);
        }
        s *= (1.0f + 4.8828125e-4f);           // cancel tf32 truncation bias on W
        ((uint32_t*)g_t)[(size_t)bm0 * 96 + o] = f2tf32(s);
    }
}

// ---------------------------------------------------------------------------
// Balanced persistent split-K tf32 GEMM. BM=512 tile: 8 warps x 64 rows
// (4 m16 subtiles/warp -> 4x b-frag reuse). 2-stage cp.async ring for W;
// B (t chunk) via LDG->register->transposed STS ([ko][kk], conflict-free reads).
// ---------------------------------------------------------------------------
extern __shared__ uint32_t smem_dyn[];

__global__ __launch_bounds__(256, 1) void gemm_kernel(const float* __restrict__ W,
                                                      float* __restrict__ out) {
    const int tid  = threadIdx.x;
    const int warp = tid >> 5, lane = tid & 31;
    const int lg   = lane >> 2, lt = lane & 3;
    const int row0 = warp * 64;

    const int wlr = tid >> 3;              // W tile: 16 rows/thread (+q*32)
    const int wlc = (tid & 7) * 4;
    const int tkk = tid >> 3;              // t chunk: 1 float4/thread
    const int tko = (tid & 7) * 4;

    int s0 = (int)(((long long)blockIdx.x * TOTAL_STEPS) / NBLK);
    const int s_end = (int)(((long long)(blockIdx.x + 1) * TOTAL_STEPS) / NBLK);

    while (s0 < s_end) {
        const int tile = s0 / CHUNKS;
        const int seg_end = min(s_end, (tile + 1) * CHUNKS);
        const int len = seg_end - s0;
        const int b  = tile >> 3;
        const int n0 = (tile & 7) * BM;
        const int kk0 = (s0 - tile * CHUNKS) * BKT;

        const float* Wbase = W   + ((size_t)(b * NN + n0)) * MJ + kk0;
        const float* Tbase = g_t + ((size_t)b * MJ + kk0) * KO;

        float acc[4][4][4];
#pragma unroll
        for (int m = 0; m < 4; ++m)
#pragma unroll
            for (int i = 0; i < 4; ++i)
#pragma unroll
                for (int j = 0; j < 4; ++j) acc[m][i][j] = 0.f;

#define FILL_W(s, t)                                                              \
    {                                                                             \
        uint32_t* Wst = smem_dyn + (s) * STAGE_WORDS;                             \
        const float* wp_ = Wbase + (t) * BKT;                                     \
        _Pragma("unroll")                                                         \
        for (int q = 0; q < 16; ++q) {                                            \
            uint32_t d_ = (uint32_t)__cvta_generic_to_shared(                     \
                &Wst[(wlr + q * 32) * WS + wlc]);                                 \
            asm volatile("cp.async.cg.shared.global [%0], [%1], 16;" ::           \
                         "r"(d_), "l"(wp_ + (size_t)(wlr + q * 32) * MJ + wlc));  \
        }                                                                         \
    }

        FILL_W(0, 0);
        asm volatile("cp.async.commit_group;");
        float4 treg = *(const float4*)(Tbase + tid * 4);

        for (int it = 0; it < len; ++it) {
            asm volatile("cp.async.wait_group 0;");   // W(it) landed (this thread)
            // transposed STS of t chunk it: Tsh[ko][kk], stride WS
            {
                uint32_t* Tst = smem_dyn + (it & 1) * STAGE_WORDS + W_WORDS;
                Tst[(tko + 0) * WS + tkk] = __float_as_uint(treg.x);
                Tst[(tko + 1) * WS + tkk] = __float_as_uint(treg.y);
                Tst[(tko + 2) * WS + tkk] = __float_as_uint(treg.z);
                Tst[(tko + 3) * WS + tkk] = __float_as_uint(treg.w);
            }
            __syncthreads();                          // tile it fully visible
            if (it + 1 < len) {
                FILL_W((it + 1) & 1, it + 1);
                treg = *(const float4*)(Tbase + (it + 1) * (BKT * KO) + tid * 4);
            }
            asm volatile("cp.async.commit_group;");

            const uint32_t* Ws = smem_dyn + (it & 1) * STAGE_WORDS;
            const uint32_t* Ts = Ws + W_WORDS;
#pragma unroll
            for (int s4 = 0; s4 < 4; ++s4) {
                const int kc = s4 * 8;
                uint32_t a[4][4];
#pragma unroll
                for (int m = 0; m < 4; ++m) {
                    int r = row0 + m * 16 + lg;
                    a[m][0] = Ws[r * WS + kc + lt];
                    a[m][1] = Ws[(r + 8) * WS + kc + lt];
                    a[m][2] = Ws[r * WS + kc + lt + 4];
                    a[m][3] = Ws[(r + 8) * WS + kc + lt + 4];
                }
#pragma unroll
                for (int nt = 0; nt < 4; ++nt) {
                    uint32_t b0 = Ts[(nt * 8 + lg) * WS + kc + lt];
                    uint32_t b1 = Ts[(nt * 8 + lg) * WS + kc + lt + 4];
#pragma unroll
                    for (int m = 0; m < 4; ++m) {
                        asm volatile(
                            "mma.sync.aligned.m16n8k8.row.col.f32.tf32.tf32.f32 "
                            "{%0,%1,%2,%3}, {%4,%5,%6,%7}, {%8,%9}, {%0,%1,%2,%3};"
                            : "+f"(acc[m][nt][0]), "+f"(acc[m][nt][1]),
                              "+f"(acc[m][nt][2]), "+f"(acc[m][nt][3])
                            : "r"(a[m][0]), "r"(a[m][1]), "r"(a[m][2]), "r"(a[m][3]),
                              "r"(b0), "r"(b1));
                    }
                }
            }
        }
#undef FILL_W

        // ---- flush segment: stage 512x32 in smem (stride 33), coalesced REDG ----
        asm volatile("cp.async.wait_group 0;");
        __syncthreads();                              // all compute done
        float* stg = (float*)smem_dyn;                // 512*33*4 = 67.6 KB
#pragma unroll
        for (int m = 0; m < 4; ++m)
#pragma unroll
            for (int nt = 0; nt < 4; ++nt) {
                int col = nt * 8 + lt * 2;
                int r = row0 + m * 16 + lg;
                stg[r * 33 + col]           = acc[m][nt][0];
                stg[r * 33 + col + 1]       = acc[m][nt][1];
                stg[(r + 8) * 33 + col]     = acc[m][nt][2];
                stg[(r + 8) * 33 + col + 1] = acc[m][nt][3];
            }
        __syncthreads();
        float* obase = out + (size_t)b * (KO * NN);
#pragma unroll
        for (int p = 0; p < 64; ++p) {
            int idx = p * 256 + tid;           // 16384 outputs
            int nl = idx & 511, k = idx >> 9;
            atomicAdd(obase + (size_t)k * NN + n0 + nl, stg[nl * 33 + k]);
        }
        __syncthreads();                        // staging freed before next FILL

        s0 = seg_end;
    }
}

// ---------------------------------------------------------------------------
extern "C" void kernel_launch(void* const* d_in, const int* in_sizes, int n_in,
                              void* d_out, int out_size) {
    const float* W  = (const float*)d_in[0];
    const float* x  = (const float*)d_in[1];
    const float* cw = (const float*)d_in[2];
    const float* cb = (const float*)d_in[3];
    float* out = (float*)d_out;

    static int attr_set = 0;
    if (!attr_set) {
        cudaFuncSetAttribute(gemm_kernel,
                             cudaFuncAttributeMaxDynamicSharedMemorySize, GEMM_SMEM);
        attr_set = 1;
    }

    precompute_t_kernel<<<(BSZ * NN) / 16, 256>>>(x, cw, out, cb);
    gemm_kernel<<<NBLK, 256, GEMM_SMEM>>>(W, out);
}

// round 10
// speedup vs baseline: 1.1421x; 1.1421x over previous
#include <cuda_runtime.h>
#include <cstdint>

#define BSZ 2
#define NN  4096
#define JJ  3
#define CC  32
#define KO  32
#define MJ  (NN*JJ)               // 12288
#define BM  256
#define BKT 32
#define NTILES (NN/BM)            // 16
#define CHUNKS (MJ/BKT)           // 384
#define TOTAL_STEPS (BSZ*NTILES*CHUNKS)   // 12288
#define NBLK 148                  // one persistent block per SM
#define WS  36                    // padded stride (conflict-free a-frags)
#define STAGES 5
#define STAGE_WORDS ((BM + BKT) * WS)         // 10368
#define GEMM_SMEM (STAGES * STAGE_WORDS * 4)  // 207360 B

__device__ float g_t[BSZ * MJ * KO];          // t[b][mj][k] (tf32 bits)

__device__ __forceinline__ uint32_t f2tf32(float f) {
    uint32_t o;
    asm("cvt.rna.tf32.f32 %0, %1;" : "=r"(o) : "f"(f));
    return o;
}

// ---------------------------------------------------------------------------
// Fused: out[b][k][n] = bias[k]  AND  t[bm][j*32+k] = (1+2^-11)*sum_c cw*x
// ---------------------------------------------------------------------------
__global__ __launch_bounds__(256) void precompute_t_kernel(const float* __restrict__ x,
                                                           const float* __restrict__ cw,
                                                           float* __restrict__ out,
                                                           const float* __restrict__ cb) {
    __shared__ float cws[KO * 100];
    __shared__ float xs[16 * WS];

    const int tid = threadIdx.x;
    const int bm0 = blockIdx.x * 16;

    {   // out init: 512 elements per block, 2 per thread (same k)
        int idx = blockIdx.x * 512 + tid * 2;
        float bk = cb[(idx >> 12) & 31];
        *(float2*)(out + idx) = make_float2(bk, bk);
    }

#pragma unroll
    for (int p = 0; p < 3; ++p) {
        int idx = p * 256 + tid;               // 768 float4 of conv_w
        int r = idx / 24, cv = idx % 24;
        float4 v = ((const float4*)cw)[idx];
        *(float4*)(cws + r * 100 + cv * 4) = v;
    }
    if (tid < 128) {
        int r = tid >> 3, cv = tid & 7;
        float4 v = ((const float4*)(x + (size_t)bm0 * CC))[tid];
        *(float4*)(xs + r * WS + cv * 4) = v;
    }
    __syncthreads();

#pragma unroll
    for (int p = 0; p < 6; ++p) {
        int o = p * 256 + tid;                 // 0..1535
        int bm = o / 96, jk = o % 96;
        int j = jk >> 5, k = jk & 31;
        const float* xr = xs + bm * WS;
        const float* wr = cws + k * 100 + j * 32;
        float s = 0.f;
#pragma unroll
        for (int cv = 0; cv < 8; ++cv) {
            float4 xv = *(const float4*)(xr + cv * 4);
            float4 wv = *(const float4*)(wr + cv * 4);
            s = fmaf(xv.x, wv.x, s);
            s = fmaf(xv.y, wv.y, s);
            s = fmaf(xv.z, wv.z, s);
            s = fmaf(xv.w, wv.w, s);
        }
        s *= (1.0f + 4.8828125e-4f);           // cancel tf32 truncation bias on W
        ((uint32_t*)g_t)[(size_t)bm0 * 96 + o] = f2tf32(s);
    }
}

// ---------------------------------------------------------------------------
// Balanced persistent split-K tf32 GEMM, 5-stage cp.async ring (4 tiles in
// flight). BM=256: 8 warps x 32 rows (2 m16 subtiles/warp).
// ---------------------------------------------------------------------------
extern __shared__ uint32_t smem_dyn[];

__global__ __launch_bounds__(256, 1) void gemm_kernel(const float* __restrict__ W,
                                                      float* __restrict__ out) {
    const int tid  = threadIdx.x;
    const int warp = tid >> 5, lane = tid & 31;
    const int lg   = lane >> 2, lt = lane & 3;
    const int row0 = warp * 32;

    const int wlr = tid >> 3;              // W tile: 8 rows/thread (+q*32)
    const int wlc = (tid & 7) * 4;
    const int tkk = tid >> 3;              // t tile: 1 float4/thread
    const int tko = (tid & 7) * 4;

    int s0 = (int)(((long long)blockIdx.x * TOTAL_STEPS) / NBLK);
    const int s_end = (int)(((long long)(blockIdx.x + 1) * TOTAL_STEPS) / NBLK);

    while (s0 < s_end) {
        const int tile = s0 / CHUNKS;
        const int seg_end = min(s_end, (tile + 1) * CHUNKS);
        const int len = seg_end - s0;
        const int b  = tile >> 4;
        const int n0 = (tile & 15) * BM;
        const int kk0 = (s0 - tile * CHUNKS) * BKT;

        const float* Wbase = W   + ((size_t)(b * NN + n0)) * MJ + kk0;
        const float* Tbase = g_t + ((size_t)b * MJ + kk0) * KO;

        float acc[2][4][4];
#pragma unroll
        for (int m = 0; m < 2; ++m)
#pragma unroll
            for (int i = 0; i < 4; ++i)
#pragma unroll
                for (int j = 0; j < 4; ++j) acc[m][i][j] = 0.f;

#define FILL(s, t)                                                                \
    {                                                                             \
        uint32_t* Wst = smem_dyn + (s) * STAGE_WORDS;                             \
        uint32_t* Tst = Wst + BM * WS;                                            \
        const float* wp_ = Wbase + (t) * BKT;                                     \
        _Pragma("unroll")                                                         \
        for (int q = 0; q < 8; ++q) {                                             \
            uint32_t d_ = (uint32_t)__cvta_generic_to_shared(                     \
                &Wst[(wlr + q * 32) * WS + wlc]);                                 \
            asm volatile("cp.async.cg.shared.global [%0], [%1], 16;" ::           \
                         "r"(d_), "l"(wp_ + (size_t)(wlr + q * 32) * MJ + wlc));  \
        }                                                                         \
        uint32_t dt_ = (uint32_t)__cvta_generic_to_shared(                        \
            &Tst[tkk * WS + tko]);                                                \
        asm volatile("cp.async.cg.shared.global [%0], [%1], 16;" ::               \
                     "r"(dt_), "l"(Tbase + (t) * (BKT * KO) + tid * 4));          \
    }

        // prefill up to 4 tiles, one commit group each
#pragma unroll
        for (int pf = 0; pf < 4; ++pf) {
            if (pf < len) FILL(pf, pf);
            asm volatile("cp.async.commit_group;");
        }

        for (int it = 0; it < len; ++it) {
            asm volatile("cp.async.wait_group 3;");   // oldest tile landed
            __syncthreads();                          // visible; compute(it-1) done
            if (it + 4 < len) FILL((it + 4) % STAGES, it + 4);
            asm volatile("cp.async.commit_group;");

            const uint32_t* Ws = smem_dyn + (it % STAGES) * STAGE_WORDS;
            const uint32_t* Ts = Ws + BM * WS;
#pragma unroll
            for (int s4 = 0; s4 < 4; ++s4) {
                const int kc = s4 * 8;
                uint32_t a[2][4];
#pragma unroll
                for (int m = 0; m < 2; ++m) {
                    int r = row0 + m * 16 + lg;
                    a[m][0] = Ws[r * WS + kc + lt];
                    a[m][1] = Ws[(r + 8) * WS + kc + lt];
                    a[m][2] = Ws[r * WS + kc + lt + 4];
                    a[m][3] = Ws[(r + 8) * WS + kc + lt + 4];
                }
#pragma unroll
                for (int nt = 0; nt < 4; ++nt) {
                    uint32_t b0 = Ts[(kc + lt)     * WS + nt * 8 + lg];
                    uint32_t b1 = Ts[(kc + lt + 4) * WS + nt * 8 + lg];
#pragma unroll
                    for (int m = 0; m < 2; ++m) {
                        asm volatile(
                            "mma.sync.aligned.m16n8k8.row.col.f32.tf32.tf32.f32 "
                            "{%0,%1,%2,%3}, {%4,%5,%6,%7}, {%8,%9}, {%0,%1,%2,%3};"
                            : "+f"(acc[m][nt][0]), "+f"(acc[m][nt][1]),
                              "+f"(acc[m][nt][2]), "+f"(acc[m][nt][3])
                            : "r"(a[m][0]), "r"(a[m][1]), "r"(a[m][2]), "r"(a[m][3]),
                              "r"(b0), "r"(b1));
                    }
                }
            }
        }
#undef FILL

        // ---- flush segment: stage 256x32 in smem (stride 33), coalesced REDG ----
        asm volatile("cp.async.wait_group 0;");
        __syncthreads();
        float* stg = (float*)smem_dyn;                // 33.8 KB
#pragma unroll
        for (int m = 0; m < 2; ++m)
#pragma unroll
            for (int nt = 0; nt < 4; ++nt) {
                int col = nt * 8 + lt * 2;
                int r = row0 + m * 16 + lg;
                stg[r * 33 + col]           = acc[m][nt][0];
                stg[r * 33 + col + 1]       = acc[m][nt][1];
                stg[(r + 8) * 33 + col]     = acc[m][nt][2];
                stg[(r + 8) * 33 + col + 1] = acc[m][nt][3];
            }
        __syncthreads();
        float* obase = out + (size_t)b * (KO * NN);
#pragma unroll
        for (int p = 0; p < 32; ++p) {
            int idx = p * 256 + tid;           // 8192 outputs
            int nl = idx & 255, k = idx >> 8;
            atomicAdd(obase + (size_t)k * NN + n0 + nl, stg[nl * 33 + k]);
        }
        __syncthreads();                        // staging freed before next FILL

        s0 = seg_end;
    }
}

// ---------------------------------------------------------------------------
extern "C" void kernel_launch(void* const* d_in, const int* in_sizes, int n_in,
                              void* d_out, int out_size) {
    const float* W  = (const float*)d_in[0];
    const float* x  = (const float*)d_in[1];
    const float* cw = (const float*)d_in[2];
    const float* cb = (const float*)d_in[3];
    float* out = (float*)d_out;

    static int attr_set = 0;
    if (!attr_set) {
        cudaFuncSetAttribute(gemm_kernel,
                             cudaFuncAttributeMaxDynamicSharedMemorySize, GEMM_SMEM);
        attr_set = 1;
    }

    precompute_t_kernel<<<(BSZ * NN) / 16, 256>>>(x, cw, out, cb);
    gemm_kernel<<<NBLK, 256, GEMM_SMEM>>>(W, out);
}